// round 12
// baseline (speedup 1.0000x reference)
#include <cuda_runtime.h>
#include <cuda_fp16.h>
#include <math.h>
#include <stdint.h>

// Problem constants (shape-specialized)
#define BB 4
#define NN 16384
#define CC 512
#define HH 8
#define DD 64
#define NT (BB*NN)     // 65536 rows
#define W3 (3*CC)      // 1536

#define FREQ_COEF (-0.20762050593046014f)
#define QSCALE 1048576.0f          // 2^20
#define QSCALE_INV (1.0f/1048576.0f)

// Scratch (device globals: allocation-free rule)
__device__ __half g_xh[(size_t)NT*CC];     // x as half
__device__ __half g_q[(size_t)BB*HH*NN*DD];
__device__ __half g_k[(size_t)BB*HH*NN*DD];
__device__ __half g_v[(size_t)BB*HH*NN*DD];
__device__ __half g_attn[(size_t)NT*CC];   // holds q'' = z*q*2^20, [n][h*64+d]
__device__ float  g_kv[BB*HH*DD*DD];
__device__ float  g_ksum[BB*HH*DD];
__device__ float  g_trig[128*16*2];        // [pos][fi][{cos,sin}]
__device__ __half g_wt1[(size_t)W3*CC];    // w_qkv^T  [n][k] half
__device__ __half g_mt[(size_t)BB*CC*CC];  // M^T per b: [b][j][h*64+d] half

// ---------------------------------------------------------------------------
// helpers
// ---------------------------------------------------------------------------
__device__ __forceinline__ uint32_t smem_u32(const void* p) {
    uint32_t a;
    asm("{ .reg .u64 t; cvta.to.shared.u64 t, %1; cvt.u32.u64 %0, t; }"
        : "=r"(a) : "l"(p));
    return a;
}

#define CP_ASYNC_16(sa, gp) \
    asm volatile("cp.async.cg.shared.global [%0], [%1], 16;" :: "r"(sa), "l"(gp))

#define MBAR_INIT(addr, cnt) \
    asm volatile("mbarrier.init.shared.b64 [%0], %1;" :: "r"(addr), "r"(cnt) : "memory")

// arrive triggered when all of this thread's prior cp.async complete (.noinc:
// completion counted against the init expected-count)
#define CPA_MBAR_ARRIVE(addr) \
    asm volatile("cp.async.mbarrier.arrive.noinc.shared.b64 [%0];" :: "r"(addr) : "memory")

#define MBAR_ARRIVE(addr) \
    asm volatile("mbarrier.arrive.shared.b64 _, [%0];" :: "r"(addr) : "memory")

#define MBAR_WAIT(mbar_smem_addr, phase_parity) do { \
    uint32_t _mbar = (uint32_t)(mbar_smem_addr); \
    uint32_t _parity = (uint32_t)(phase_parity); \
    uint32_t _done; \
    asm volatile( \
        "{\n\t.reg .pred p;\n\t" \
        "mbarrier.try_wait.parity.acquire.cta.shared::cta.b64 p, [%1], %2;\n\t" \
        "selp.b32 %0, 1, 0, p;\n\t}" \
        : "=r"(_done) : "r"(_mbar), "r"(_parity) : "memory"); \
    if (!_done) { \
        asm volatile( \
            "{\n\t.reg .pred P1;\n\t" \
            "WAIT_LOOP_%=:\n\t" \
            "mbarrier.try_wait.parity.acquire.cta.shared::cta.b64 P1, [%0], %1, 0x989680;\n\t" \
            "@P1 bra.uni WAIT_DONE_%=;\n\t" \
            "bra.uni WAIT_LOOP_%=;\n\t" \
            "WAIT_DONE_%=:\n\t}" \
            :: "r"(_mbar), "r"(_parity) : "memory"); \
    } \
} while(0)

__device__ __forceinline__ void ldsm_x4(unsigned* r, uint32_t addr) {
    asm volatile("ldmatrix.sync.aligned.m8n8.x4.shared.b16 {%0,%1,%2,%3}, [%4];"
        : "=r"(r[0]), "=r"(r[1]), "=r"(r[2]), "=r"(r[3]) : "r"(addr));
}
__device__ __forceinline__ void ldsm_x4_t(unsigned* r, uint32_t addr) {
    asm volatile("ldmatrix.sync.aligned.m8n8.x4.trans.shared.b16 {%0,%1,%2,%3}, [%4];"
        : "=r"(r[0]), "=r"(r[1]), "=r"(r[2]), "=r"(r[3]) : "r"(addr));
}

// fp16 mma m16n8k16, fp32 accumulate
__device__ __forceinline__ void mma16(float* c, const unsigned* a, const unsigned* b) {
    asm volatile(
        "mma.sync.aligned.m16n8k16.row.col.f32.f16.f16.f32 "
        "{%0,%1,%2,%3},{%4,%5,%6,%7},{%8,%9},{%0,%1,%2,%3};\n"
        : "+f"(c[0]), "+f"(c[1]), "+f"(c[2]), "+f"(c[3])
        : "r"(a[0]), "r"(a[1]), "r"(a[2]), "r"(a[3]), "r"(b[0]), "r"(b[1]));
}

// ---------------------------------------------------------------------------
// init: zero kv/ksum + trig table (runs every launch: graph replays)
// ---------------------------------------------------------------------------
__global__ void init_kernel() {
    int i = blockIdx.x * blockDim.x + threadIdx.x;
    if (i < BB*HH*DD*DD) g_kv[i] = 0.f;
    if (i < BB*HH*DD)    g_ksum[i] = 0.f;
    if (i < 128*16) {
        int pos = i >> 4, fi = i & 15;
        float freq = exp2f((float)fi * FREQ_COEF);
        float s, c;
        sincosf((float)pos * freq, &s, &c);
        g_trig[i*2]   = c;
        g_trig[i*2+1] = s;
    }
}

// ---------------------------------------------------------------------------
// convert x fp32 -> half mirror (8 elems/thread)
// ---------------------------------------------------------------------------
__global__ void convert_x_kernel(const float* __restrict__ x) {
    const size_t i = ((size_t)blockIdx.x * 256 + threadIdx.x) * 8;
    float4 a = *(const float4*)(x + i);
    float4 b = *(const float4*)(x + i + 4);
    __half2 h0 = __floats2half2_rn(a.x, a.y);
    __half2 h1 = __floats2half2_rn(a.z, a.w);
    __half2 h2 = __floats2half2_rn(b.x, b.y);
    __half2 h3 = __floats2half2_rn(b.z, b.w);
    *(uint4*)(g_xh + i) = make_uint4(*(unsigned*)&h0, *(unsigned*)&h1,
                                     *(unsigned*)&h2, *(unsigned*)&h3);
}

// ---------------------------------------------------------------------------
// Transpose weights to K-major half: src fp32 [512][N] -> dst half [N][512]
// ---------------------------------------------------------------------------
__global__ void transpose_w_kernel(const float* __restrict__ src,
                                   __half* __restrict__ dst, int N) {
    __shared__ float tile[32][33];
    const int k0 = blockIdx.y << 5, n0 = blockIdx.x << 5;
    const int tx = threadIdx.x, ty = threadIdx.y;   // 32 x 8
#pragma unroll
    for (int i = 0; i < 32; i += 8)
        tile[ty+i][tx] = src[(size_t)(k0+ty+i)*N + n0 + tx];
    __syncthreads();
#pragma unroll
    for (int i = 0; i < 32; i += 8)
        dst[(size_t)(n0+ty+i)*CC + k0 + tx] = __float2half_rn(tile[tx][ty+i]);
}

// ---------------------------------------------------------------------------
// Pipelined fp16 GEMM core: 3-stage cp.async + mbarrier pipeline (warps drift),
// tile 128x128, warp 64x32, K=64. Stage = A[128][72] + B[128][72] halves.
// ---------------------------------------------------------------------------
#define TIL_H 9216             // halves per tile (128*72)
#define STG_H (2*TIL_H)        // halves per stage (A+B)
#define SMEM_PIPE_BYTES (3 * STG_H * 2)   // 110592

__device__ __forceinline__ void issue_stage(
    uint32_t smbase, int stage, const __half* gA, const __half* gB,
    int m0, int n0, int k0, int tid)
{
    const uint32_t stB = smbase + stage*(STG_H*2);
#pragma unroll
    for (int i = 0; i < 4; i++) {
        const int lin = i*256 + tid;          // 1024 chunks per tile
        const int row = lin >> 3;
        const int c8  = (lin & 7) << 3;       // halves
        CP_ASYNC_16(stB + (row*72 + c8)*2,
                    gA + (size_t)(m0 + row)*CC + k0 + c8);
        CP_ASYNC_16(stB + (TIL_H + row*72 + c8)*2,
                    gB + (size_t)(n0 + row)*CC + k0 + c8);
    }
}

__device__ __forceinline__ void compute_stage(
    uint32_t aBase, uint32_t bBase, int stage, float c[4][4][4])
{
    const uint32_t aS = aBase + stage*(STG_H*2);
    const uint32_t bS = bBase + stage*(STG_H*2);
#pragma unroll
    for (int kk = 0; kk < 64; kk += 16) {
        unsigned a[4][4], b[2][4];
#pragma unroll
        for (int mf = 0; mf < 4; mf++)
            ldsm_x4(a[mf], aS + (mf*16*72 + kk)*2);
#pragma unroll
        for (int p = 0; p < 2; p++)
            ldsm_x4(b[p], bS + (p*16*72 + kk)*2);
#pragma unroll
        for (int mf = 0; mf < 4; mf++)
#pragma unroll
            for (int nf = 0; nf < 4; nf++)
                mma16(c[mf][nf], a[mf], &b[nf >> 1][(nf & 1) * 2]);
    }
}

__device__ __forceinline__ uint32_t a_frag_base(uint32_t smbase, int wm, int lane) {
    return smbase + ((wm + (lane & 15))*72 + ((lane >> 4) << 3))*2;
}
__device__ __forceinline__ uint32_t b_frag_base(uint32_t smbase, int wn, int lane) {
    return smbase + TIL_H*2 +
        ((wn + ((lane >> 4) << 3) + (lane & 7))*72 + (((lane >> 3) & 1) << 3))*2;
}

// mbarrier pipeline driver: S stages total, 3 buffers.
// full[b]: completes when all 256 threads' copies landed (noinc, count 256)
// empty[b]: completes when all 256 threads finished reading (count 256)
#define PIPE_LOOP(S, ISSUE, COMPUTE)                                          \
    do {                                                                      \
        if (tid == 0) {                                                       \
            for (int i = 0; i < 3; i++) {                                     \
                MBAR_INIT(mbF + i*8, 256);                                    \
                MBAR_INIT(mbE + i*8, 256);                                    \
            }                                                                 \
        }                                                                     \
        __syncthreads();                                                      \
        ISSUE(0); CPA_MBAR_ARRIVE(mbF);                                       \
        ISSUE(1); CPA_MBAR_ARRIVE(mbF + 8);                                   \
        for (int s = 0; s < (S); s++) {                                       \
            const int buf = s % 3;                                            \
            const int t = s + 2;                                              \
            if (t < (S)) {                                                    \
                if (t >= 3) MBAR_WAIT(mbE + (t%3)*8, ((t/3) - 1) & 1);        \
                ISSUE(t); CPA_MBAR_ARRIVE(mbF + (t%3)*8);                     \
            }                                                                 \
            MBAR_WAIT(mbF + buf*8, (s/3) & 1);                                \
            COMPUTE(buf);                                                     \
            MBAR_ARRIVE(mbE + buf*8);                                         \
        }                                                                     \
    } while (0)

// ---------------------------------------------------------------------------
// GEMM1: qkv = x @ w_qkv + b_qkv, fused RoPE + elu+1, scatter half q/k/v.
// ---------------------------------------------------------------------------
__global__ __launch_bounds__(256, 2) void gemm_qkv_kernel(
    const float* __restrict__ bias)
{
    extern __shared__ __half smp[];
    __shared__ __align__(8) uint64_t mbars[6];
    const uint32_t smbase = smem_u32(smp);
    const uint32_t mbF = smem_u32(&mbars[0]);
    const uint32_t mbE = smem_u32(&mbars[3]);
    const int tid  = threadIdx.x;
    const int warp = tid >> 5, lane = tid & 31;
    const int gid  = lane >> 2, tig = lane & 3;
    const int m0 = blockIdx.y << 7, n0 = blockIdx.x << 7;
    const int wm = (warp >> 2) << 6;
    const int wn = (warp & 3) << 5;

    const uint32_t aB = a_frag_base(smbase, wm, lane);
    const uint32_t bB = b_frag_base(smbase, wn, lane);

    float c[4][4][4];
#pragma unroll
    for (int i = 0; i < 4; i++)
#pragma unroll
        for (int j = 0; j < 4; j++)
#pragma unroll
            for (int r = 0; r < 4; r++) c[i][j][r] = 0.f;

#define G1_ISSUE(t)   issue_stage(smbase, (t)%3, g_xh, g_wt1, m0, n0, (t)*64, tid)
#define G1_COMPUTE(b) compute_stage(aB, bB, (b), c)
    PIPE_LOOP(8, G1_ISSUE, G1_COMPUTE);
#undef G1_ISSUE
#undef G1_COMPUTE

    const int sect = n0 >> 9;             // 0=q 1=k 2=v
#pragma unroll
    for (int nf = 0; nf < 4; nf++) {
        const int col = n0 + wn + nf*8 + 2*tig;
        const int h   = (col >> 6) & 7;
        const int d   = col & 63;
        const float b0v = bias[col], b1v = bias[col+1];
        const int  fi  = (d & 31) >> 1;
        const bool axx = (d < 32);
#pragma unroll
        for (int mf = 0; mf < 4; mf++) {
#pragma unroll
            for (int hf = 0; hf < 2; hf++) {
                const int r    = m0 + wm + mf*16 + gid + 8*hf;
                const int bidx = r >> 14;
                const int t    = r & (NN-1);
                float v0 = c[mf][nf][2*hf]   + b0v;
                float v1 = c[mf][nf][2*hf+1] + b1v;
                const size_t base = ((size_t)(bidx*HH + h)*NN + t)*DD + d;
                if (sect == 2) {
                    *(__half2*)(g_v + base) = __floats2half2_rn(v0, v1);
                } else {
                    const int pos = axx ? (t & 127) : (t >> 7);
                    const float2 cs = *(const float2*)(g_trig + ((pos << 4) + fi)*2);
                    float orr = v0*cs.x - v1*cs.y;
                    float oii = v0*cs.y + v1*cs.x;
                    orr = (orr > 0.f) ? orr + 1.f : __expf(orr);
                    oii = (oii > 0.f) ? oii + 1.f : __expf(oii);
                    __half* dst = (sect == 0) ? g_q : g_k;
                    *(__half2*)(dst + base) = __floats2half2_rn(orr, oii);
                }
            }
        }
    }
}

// ---------------------------------------------------------------------------
// GEMM2: out = q'' @ M_stack[b] * 2^-20 + b_proj
// ---------------------------------------------------------------------------
__global__ __launch_bounds__(256, 2) void gemm_proj_kernel(
    const float* __restrict__ bias,
    float* __restrict__ out)
{
    extern __shared__ __half smp[];
    __shared__ __align__(8) uint64_t mbars[6];
    const uint32_t smbase = smem_u32(smp);
    const uint32_t mbF = smem_u32(&mbars[0]);
    const uint32_t mbE = smem_u32(&mbars[3]);
    const int tid  = threadIdx.x;
    const int warp = tid >> 5, lane = tid & 31;
    const int gid  = lane >> 2, tig = lane & 3;
    const int m0 = blockIdx.y << 7, n0 = blockIdx.x << 7;
    const int wm = (warp >> 2) << 6;
    const int wn = (warp & 3) << 5;
    const __half* gB = g_mt + (size_t)(blockIdx.y >> 7)*CC*CC;

    const uint32_t aB = a_frag_base(smbase, wm, lane);
    const uint32_t bB = b_frag_base(smbase, wn, lane);

    float c[4][4][4];
#pragma unroll
    for (int i = 0; i < 4; i++)
#pragma unroll
        for (int j = 0; j < 4; j++)
#pragma unroll
            for (int r = 0; r < 4; r++) c[i][j][r] = 0.f;

#define G2_ISSUE(t)   issue_stage(smbase, (t)%3, g_attn, gB, m0, n0, (t)*64, tid)
#define G2_COMPUTE(b) compute_stage(aB, bB, (b), c)
    PIPE_LOOP(8, G2_ISSUE, G2_COMPUTE);
#undef G2_ISSUE
#undef G2_COMPUTE

#pragma unroll
    for (int nf = 0; nf < 4; nf++) {
        const int col = n0 + wn + nf*8 + 2*tig;
        const float b0v = bias[col], b1v = bias[col+1];
#pragma unroll
        for (int mf = 0; mf < 4; mf++) {
#pragma unroll
            for (int hf = 0; hf < 2; hf++) {
                const int r = m0 + wm + mf*16 + gid + 8*hf;
                *(float2*)(out + (size_t)r*CC + col) =
                    make_float2(c[mf][nf][2*hf]*QSCALE_INV + b0v,
                                c[mf][nf][2*hf+1]*QSCALE_INV + b1v);
            }
        }
    }
}

// ---------------------------------------------------------------------------
// kv[b,h,d,e] = sum_n k[n,d] v[n,e];  ksum via ones-column (col 64).
// fp16 mma, trans-ldmatrix, 3-stage cp.async + mbarrier pipeline.
// ---------------------------------------------------------------------------
#define KT_S 72   // k tile stride (halves)
#define VT_S 88   // v tile stride (halves)
#define KV_STG_H (64*KT_S + 64*VT_S)     // 10240 halves per stage
#define KV_SMEM_BYTES (3 * KV_STG_H * 2) // 61440

__device__ __forceinline__ void kv_issue(
    uint32_t smbase, int stage, const __half* kb, const __half* vb,
    int n0, int tid)
{
    const uint32_t stB = smbase + stage*(KV_STG_H*2);
#pragma unroll
    for (int i = 0; i < 2; i++) {
        const int lin = i*256 + tid;
        const int row = lin >> 3, c8 = (lin & 7) << 3;
        CP_ASYNC_16(stB + (row*KT_S + c8)*2,
                    kb + (size_t)(n0 + row)*DD + c8);
        CP_ASYNC_16(stB + (64*KT_S + row*VT_S + c8)*2,
                    vb + (size_t)(n0 + row)*DD + c8);
    }
}

__global__ __launch_bounds__(256, 2) void kv_mma_kernel() {
    extern __shared__ __half kvsm[];
    __shared__ __align__(8) uint64_t mbars[6];
    const uint32_t smbase = smem_u32(kvsm);
    const uint32_t mbF = smem_u32(&mbars[0]);
    const uint32_t mbE = smem_u32(&mbars[3]);

    const int tid  = threadIdx.x;
    const int warp = tid >> 5, lane = tid & 31;
    const int gid  = lane >> 2, tig = lane & 3;
    const int bh    = blockIdx.x;
    const int nbase = blockIdx.y << 10;
    const int d0   = (warp & 3) << 4;     // m-tile (d)
    const int srow = (warp >> 2) << 5;    // seq slice 0/32

    if (tid < 64) {
#pragma unroll
        for (int st = 0; st < 3; st++) {
            __half* Vt = kvsm + st*KV_STG_H + 64*KT_S;
            Vt[tid*VT_S + 64] = __float2half(1.f);
#pragma unroll
            for (int j = 65; j < 80; j++) Vt[tid*VT_S + j] = __float2half(0.f);
        }
    }
    __syncthreads();

    float c[9][4];
#pragma unroll
    for (int t = 0; t < 9; t++)
#pragma unroll
        for (int r = 0; r < 4; r++) c[t][r] = 0.f;

    const __half* kb = g_k + (size_t)bh*NN*DD;
    const __half* vb = g_v + (size_t)bh*NN*DD;

    const int at_row = ((lane >> 4) << 3) + (lane & 7);
    const int at_col = d0 + (((lane >> 3) & 1) << 3);
    const int bt_row = (((lane >> 3) & 1) << 3) + (lane & 7);
    const int bt_coff = ((lane >> 4) << 3);

#define KV_ISSUE(t) kv_issue(smbase, (t)%3, kb, vb, nbase + (t)*64, tid)
#define KV_COMPUTE(bufi)                                                       \
    do {                                                                       \
        const uint32_t ktB = smbase + (bufi)*(KV_STG_H*2);                     \
        const uint32_t vtB = ktB + 64*KT_S*2;                                  \
        _Pragma("unroll")                                                      \
        for (int ks = 0; ks < 2; ks++) {                                       \
            const int s16 = srow + ks*16;                                      \
            unsigned a[4], b[5][4];                                            \
            ldsm_x4_t(a, ktB + ((s16 + at_row)*KT_S + at_col)*2);              \
            _Pragma("unroll")                                                  \
            for (int bt = 0; bt < 5; bt++)                                     \
                ldsm_x4_t(b[bt], vtB + ((s16 + bt_row)*VT_S + bt*16 + bt_coff)*2); \
            _Pragma("unroll")                                                  \
            for (int t2 = 0; t2 < 9; t2++)                                     \
                mma16(c[t2], a, &b[t2 >> 1][(t2 & 1) * 2]);                    \
        }                                                                      \
    } while (0)
    PIPE_LOOP(16, KV_ISSUE, KV_COMPUTE);
#undef KV_ISSUE
#undef KV_COMPUTE

    float* kvp = g_kv + bh*DD*DD;
#pragma unroll
    for (int t = 0; t < 8; t++) {
        const int e = t*8 + 2*tig;
        atomicAdd(&kvp[(d0+gid)*DD + e],       c[t][0]);
        atomicAdd(&kvp[(d0+gid)*DD + e + 1],   c[t][1]);
        atomicAdd(&kvp[(d0+gid+8)*DD + e],     c[t][2]);
        atomicAdd(&kvp[(d0+gid+8)*DD + e + 1], c[t][3]);
    }
    if (tig == 0) {
        atomicAdd(&g_ksum[bh*DD + d0 + gid],     c[8][0]);
        atomicAdd(&g_ksum[bh*DD + d0 + gid + 8], c[8][2]);
    }
}

// ---------------------------------------------------------------------------
// M^T[b][j][h*64+d] = sum_e kv[b,h,d,e] * w_proj[h*64+e, j]   (half out)
// ---------------------------------------------------------------------------
__global__ __launch_bounds__(256) void m_precompute_kernel(
    const float* __restrict__ w_proj)
{
    __shared__ float kvs[64][65];
    __shared__ float ws[64][65];
    const int b = blockIdx.x, h = blockIdx.y, j0 = blockIdx.z << 6;
    const int tid = threadIdx.x;
    const float* kvp = g_kv + ((b*HH + h)*DD*DD);

#pragma unroll
    for (int i = 0; i < 16; i++) {
        const int lin = i*256 + tid;          // 4096
        const int r = lin >> 6, cidx = lin & 63;
        kvs[r][cidx] = kvp[r*DD + cidx];
        ws[r][cidx]  = w_proj[(size_t)(h*DD + r)*CC + j0 + cidx];
    }
    __syncthreads();

    const int d = tid & 63;
    const int jg = tid >> 6;                  // 0..3
#pragma unroll
    for (int jj = 0; jj < 16; jj++) {
        const int j = jg*16 + jj;
        float acc = 0.f;
#pragma unroll
        for (int e = 0; e < 64; e++)
            acc = fmaf(kvs[d][e], ws[e][j], acc);
        g_mt[((size_t)b*CC + j0 + j)*CC + h*DD + d] = __float2half_rn(acc);
    }
}

// ---------------------------------------------------------------------------
// q''[b*NN+n][h*64+d] = q[b,h,n,d] * 2^20 / (q.ksum + 1e-6)
// ---------------------------------------------------------------------------
__global__ __launch_bounds__(256) void zq_kernel() {
    const int bh = blockIdx.x, b = bh >> 3, h = bh & 7;
    const int tid = threadIdx.x;
    const int r8 = tid >> 3;
    const int t8 = tid & 7;
    const int n  = (blockIdx.y << 5) + r8;

    uint4 u = *(const uint4*)(g_q + ((size_t)bh*NN + n)*DD + t8*8);
    float f[8];
    {
        __half2* hp = (__half2*)&u;
#pragma unroll
        for (int i = 0; i < 4; i++) {
            float2 t = __half22float2(hp[i]);
            f[2*i] = t.x; f[2*i+1] = t.y;
        }
    }
    const float* ks = g_ksum + bh*DD + t8*8;
    float dot = 0.f;
#pragma unroll
    for (int i = 0; i < 8; i++) dot = fmaf(f[i], ks[i], dot);
    dot += __shfl_xor_sync(0xffffffffu, dot, 1);
    dot += __shfl_xor_sync(0xffffffffu, dot, 2);
    dot += __shfl_xor_sync(0xffffffffu, dot, 4);
    const float z = QSCALE / (dot + 1e-6f);

    __half2 o[4];
#pragma unroll
    for (int i = 0; i < 4; i++)
        o[i] = __floats2half2_rn(f[2*i]*z, f[2*i+1]*z);
    *(uint4*)(g_attn + ((size_t)b*NN + n)*CC + h*DD + t8*8) =
        *(uint4*)o;
}

// ---------------------------------------------------------------------------
extern "C" void kernel_launch(void* const* d_in, const int* in_sizes, int n_in,
                              void* d_out, int out_size) {
    const float* x      = (const float*)d_in[0];
    const float* w_qkv  = (const float*)d_in[1];
    const float* b_qkv  = (const float*)d_in[2];
    const float* w_proj = (const float*)d_in[3];
    const float* b_proj = (const float*)d_in[4];
    float* out = (float*)d_out;

    cudaFuncSetAttribute(gemm_qkv_kernel,
        cudaFuncAttributeMaxDynamicSharedMemorySize, SMEM_PIPE_BYTES);
    cudaFuncSetAttribute(gemm_proj_kernel,
        cudaFuncAttributeMaxDynamicSharedMemorySize, SMEM_PIPE_BYTES);
    cudaFuncSetAttribute(kv_mma_kernel,
        cudaFuncAttributeMaxDynamicSharedMemorySize, KV_SMEM_BYTES);

    __half* wt1p;
    cudaGetSymbolAddress((void**)&wt1p, g_wt1);

    init_kernel<<<512, 256>>>();
    convert_x_kernel<<<16384, 256>>>(x);
    transpose_w_kernel<<<dim3(48, 16), dim3(32, 8)>>>(w_qkv, wt1p, W3);
    gemm_qkv_kernel<<<dim3(12, 512), 256, SMEM_PIPE_BYTES>>>(b_qkv);
    kv_mma_kernel<<<dim3(32, 16), 256, KV_SMEM_BYTES>>>();
    m_precompute_kernel<<<dim3(4, 8, 8), 256>>>(w_proj);
    zq_kernel<<<dim3(32, 512), 256>>>();
    gemm_proj_kernel<<<dim3(4, 512), 256, SMEM_PIPE_BYTES>>>(b_proj, out);
}

// round 13
// speedup vs baseline: 1.0012x; 1.0012x over previous
#include <cuda_runtime.h>
#include <cuda_fp16.h>
#include <math.h>
#include <stdint.h>

// Problem constants (shape-specialized)
#define BB 4
#define NN 16384
#define CC 512
#define HH 8
#define DD 64
#define NT (BB*NN)     // 65536 rows
#define W3 (3*CC)      // 1536

#define FREQ_COEF (-0.20762050593046014f)
#define QSCALE 1048576.0f          // 2^20
#define QSCALE_INV (1.0f/1048576.0f)

// Scratch (device globals: allocation-free rule)
__device__ __half g_xh[(size_t)NT*CC];     // x as half
__device__ __half g_q[(size_t)BB*HH*NN*DD];
__device__ __half g_k[(size_t)BB*HH*NN*DD];
__device__ __half g_v[(size_t)BB*HH*NN*DD];
__device__ __half g_attn[(size_t)NT*CC];   // holds q'' = z*q*2^20, [n][h*64+d]
__device__ float  g_kv[BB*HH*DD*DD];
__device__ float  g_ksum[BB*HH*DD];
__device__ float  g_trig[128*16*2];        // [pos][fi][{cos,sin}]
__device__ __half g_wt1[(size_t)W3*CC];    // w_qkv^T  [n][k] half
__device__ __half g_mt[(size_t)BB*CC*CC];  // M^T per b: [b][j][h*64+d] half

// ---------------------------------------------------------------------------
// helpers
// ---------------------------------------------------------------------------
__device__ __forceinline__ uint32_t smem_u32(const void* p) {
    uint32_t a;
    asm("{ .reg .u64 t; cvta.to.shared.u64 t, %1; cvt.u32.u64 %0, t; }"
        : "=r"(a) : "l"(p));
    return a;
}

#define CP_ASYNC_16(sa, gp) \
    asm volatile("cp.async.cg.shared.global [%0], [%1], 16;" :: "r"(sa), "l"(gp))

#define MBAR_INIT(addr, cnt) \
    asm volatile("mbarrier.init.shared.b64 [%0], %1;" :: "r"(addr), "r"(cnt) : "memory")

// arrive triggered when all of this thread's prior cp.async complete (.noinc:
// completion counted against the init expected-count)
#define CPA_MBAR_ARRIVE(addr) \
    asm volatile("cp.async.mbarrier.arrive.noinc.shared.b64 [%0];" :: "r"(addr) : "memory")

#define MBAR_ARRIVE(addr) \
    asm volatile("mbarrier.arrive.shared.b64 _, [%0];" :: "r"(addr) : "memory")

#define MBAR_WAIT(mbar_smem_addr, phase_parity) do { \
    uint32_t _mbar = (uint32_t)(mbar_smem_addr); \
    uint32_t _parity = (uint32_t)(phase_parity); \
    uint32_t _done; \
    asm volatile( \
        "{\n\t.reg .pred p;\n\t" \
        "mbarrier.try_wait.parity.acquire.cta.shared::cta.b64 p, [%1], %2;\n\t" \
        "selp.b32 %0, 1, 0, p;\n\t}" \
        : "=r"(_done) : "r"(_mbar), "r"(_parity) : "memory"); \
    if (!_done) { \
        asm volatile( \
            "{\n\t.reg .pred P1;\n\t" \
            "WAIT_LOOP_%=:\n\t" \
            "mbarrier.try_wait.parity.acquire.cta.shared::cta.b64 P1, [%0], %1, 0x989680;\n\t" \
            "@P1 bra.uni WAIT_DONE_%=;\n\t" \
            "bra.uni WAIT_LOOP_%=;\n\t" \
            "WAIT_DONE_%=:\n\t}" \
            :: "r"(_mbar), "r"(_parity) : "memory"); \
    } \
} while(0)

__device__ __forceinline__ void ldsm_x4(unsigned* r, uint32_t addr) {
    asm volatile("ldmatrix.sync.aligned.m8n8.x4.shared.b16 {%0,%1,%2,%3}, [%4];"
        : "=r"(r[0]), "=r"(r[1]), "=r"(r[2]), "=r"(r[3]) : "r"(addr));
}
__device__ __forceinline__ void ldsm_x4_t(unsigned* r, uint32_t addr) {
    asm volatile("ldmatrix.sync.aligned.m8n8.x4.trans.shared.b16 {%0,%1,%2,%3}, [%4];"
        : "=r"(r[0]), "=r"(r[1]), "=r"(r[2]), "=r"(r[3]) : "r"(addr));
}

// fp16 mma m16n8k16, fp32 accumulate
__device__ __forceinline__ void mma16(float* c, const unsigned* a, const unsigned* b) {
    asm volatile(
        "mma.sync.aligned.m16n8k16.row.col.f32.f16.f16.f32 "
        "{%0,%1,%2,%3},{%4,%5,%6,%7},{%8,%9},{%0,%1,%2,%3};\n"
        : "+f"(c[0]), "+f"(c[1]), "+f"(c[2]), "+f"(c[3])
        : "r"(a[0]), "r"(a[1]), "r"(a[2]), "r"(a[3]), "r"(b[0]), "r"(b[1]));
}

// ---------------------------------------------------------------------------
// init: zero kv/ksum + trig table (runs every launch: graph replays)
// ---------------------------------------------------------------------------
__global__ void init_kernel() {
    int i = blockIdx.x * blockDim.x + threadIdx.x;
    if (i < BB*HH*DD*DD) g_kv[i] = 0.f;
    if (i < BB*HH*DD)    g_ksum[i] = 0.f;
    if (i < 128*16) {
        int pos = i >> 4, fi = i & 15;
        float freq = exp2f((float)fi * FREQ_COEF);
        float s, c;
        sincosf((float)pos * freq, &s, &c);
        g_trig[i*2]   = c;
        g_trig[i*2+1] = s;
    }
}

// ---------------------------------------------------------------------------
// convert x fp32 -> half mirror (8 elems/thread)
// ---------------------------------------------------------------------------
__global__ void convert_x_kernel(const float* __restrict__ x) {
    const size_t i = ((size_t)blockIdx.x * 256 + threadIdx.x) * 8;
    float4 a = *(const float4*)(x + i);
    float4 b = *(const float4*)(x + i + 4);
    __half2 h0 = __floats2half2_rn(a.x, a.y);
    __half2 h1 = __floats2half2_rn(a.z, a.w);
    __half2 h2 = __floats2half2_rn(b.x, b.y);
    __half2 h3 = __floats2half2_rn(b.z, b.w);
    *(uint4*)(g_xh + i) = make_uint4(*(unsigned*)&h0, *(unsigned*)&h1,
                                     *(unsigned*)&h2, *(unsigned*)&h3);
}

// ---------------------------------------------------------------------------
// Transpose weights to K-major half: src fp32 [512][N] -> dst half [N][512]
// ---------------------------------------------------------------------------
__global__ void transpose_w_kernel(const float* __restrict__ src,
                                   __half* __restrict__ dst, int N) {
    __shared__ float tile[32][33];
    const int k0 = blockIdx.y << 5, n0 = blockIdx.x << 5;
    const int tx = threadIdx.x, ty = threadIdx.y;   // 32 x 8
#pragma unroll
    for (int i = 0; i < 32; i += 8)
        tile[ty+i][tx] = src[(size_t)(k0+ty+i)*N + n0 + tx];
    __syncthreads();
#pragma unroll
    for (int i = 0; i < 32; i += 8)
        dst[(size_t)(n0+ty+i)*CC + k0 + tx] = __float2half_rn(tile[tx][ty+i]);
}

// ---------------------------------------------------------------------------
// Pipelined fp16 GEMM core: 3-stage cp.async + mbarrier pipeline (warps drift),
// tile 128x128, warp 64x32, K=64. Stage = A[128][72] + B[128][72] halves.
// ---------------------------------------------------------------------------
#define TIL_H 9216             // halves per tile (128*72)
#define STG_H (2*TIL_H)        // halves per stage (A+B)
#define SMEM_PIPE_BYTES (3 * STG_H * 2)   // 110592

__device__ __forceinline__ void issue_stage(
    uint32_t smbase, int stage, const __half* gA, const __half* gB,
    int m0, int n0, int k0, int tid)
{
    const uint32_t stB = smbase + stage*(STG_H*2);
#pragma unroll
    for (int i = 0; i < 4; i++) {
        const int lin = i*256 + tid;          // 1024 chunks per tile
        const int row = lin >> 3;
        const int c8  = (lin & 7) << 3;       // halves
        CP_ASYNC_16(stB + (row*72 + c8)*2,
                    gA + (size_t)(m0 + row)*CC + k0 + c8);
        CP_ASYNC_16(stB + (TIL_H + row*72 + c8)*2,
                    gB + (size_t)(n0 + row)*CC + k0 + c8);
    }
}

__device__ __forceinline__ void compute_stage(
    uint32_t aBase, uint32_t bBase, int stage, float c[4][4][4])
{
    const uint32_t aS = aBase + stage*(STG_H*2);
    const uint32_t bS = bBase + stage*(STG_H*2);
#pragma unroll
    for (int kk = 0; kk < 64; kk += 16) {
        unsigned a[4][4], b[2][4];
#pragma unroll
        for (int mf = 0; mf < 4; mf++)
            ldsm_x4(a[mf], aS + (mf*16*72 + kk)*2);
#pragma unroll
        for (int p = 0; p < 2; p++)
            ldsm_x4(b[p], bS + (p*16*72 + kk)*2);
#pragma unroll
        for (int mf = 0; mf < 4; mf++)
#pragma unroll
            for (int nf = 0; nf < 4; nf++)
                mma16(c[mf][nf], a[mf], &b[nf >> 1][(nf & 1) * 2]);
    }
}

__device__ __forceinline__ uint32_t a_frag_base(uint32_t smbase, int wm, int lane) {
    return smbase + ((wm + (lane & 15))*72 + ((lane >> 4) << 3))*2;
}
__device__ __forceinline__ uint32_t b_frag_base(uint32_t smbase, int wn, int lane) {
    return smbase + TIL_H*2 +
        ((wn + ((lane >> 4) << 3) + (lane & 7))*72 + (((lane >> 3) & 1) << 3))*2;
}

// mbarrier pipeline driver: S stages total, 3 buffers.
// full[b]: completes when all 256 threads' copies landed (noinc, count 256)
// empty[b]: completes when all 256 threads finished reading (count 256)
#define PIPE_LOOP(S, ISSUE, COMPUTE)                                          \
    do {                                                                      \
        if (tid == 0) {                                                       \
            for (int i = 0; i < 3; i++) {                                     \
                MBAR_INIT(mbF + i*8, 256);                                    \
                MBAR_INIT(mbE + i*8, 256);                                    \
            }                                                                 \
        }                                                                     \
        __syncthreads();                                                      \
        ISSUE(0); CPA_MBAR_ARRIVE(mbF);                                       \
        ISSUE(1); CPA_MBAR_ARRIVE(mbF + 8);                                   \
        for (int s = 0; s < (S); s++) {                                       \
            const int buf = s % 3;                                            \
            const int t = s + 2;                                              \
            if (t < (S)) {                                                    \
                if (t >= 3) MBAR_WAIT(mbE + (t%3)*8, ((t/3) - 1) & 1);        \
                ISSUE(t); CPA_MBAR_ARRIVE(mbF + (t%3)*8);                     \
            }                                                                 \
            MBAR_WAIT(mbF + buf*8, (s/3) & 1);                                \
            COMPUTE(buf);                                                     \
            MBAR_ARRIVE(mbE + buf*8);                                         \
        }                                                                     \
    } while (0)

// ---------------------------------------------------------------------------
// GEMM1: qkv = x @ w_qkv + b_qkv, fused RoPE + elu+1, scatter half q/k/v.
// ---------------------------------------------------------------------------
__global__ __launch_bounds__(256, 2) void gemm_qkv_kernel(
    const float* __restrict__ bias)
{
    extern __shared__ __half smp[];
    __shared__ __align__(8) uint64_t mbars[6];
    const uint32_t smbase = smem_u32(smp);
    const uint32_t mbF = smem_u32(&mbars[0]);
    const uint32_t mbE = smem_u32(&mbars[3]);
    const int tid  = threadIdx.x;
    const int warp = tid >> 5, lane = tid & 31;
    const int gid  = lane >> 2, tig = lane & 3;
    const int m0 = blockIdx.y << 7, n0 = blockIdx.x << 7;
    const int wm = (warp >> 2) << 6;
    const int wn = (warp & 3) << 5;

    const uint32_t aB = a_frag_base(smbase, wm, lane);
    const uint32_t bB = b_frag_base(smbase, wn, lane);

    float c[4][4][4];
#pragma unroll
    for (int i = 0; i < 4; i++)
#pragma unroll
        for (int j = 0; j < 4; j++)
#pragma unroll
            for (int r = 0; r < 4; r++) c[i][j][r] = 0.f;

#define G1_ISSUE(t)   issue_stage(smbase, (t)%3, g_xh, g_wt1, m0, n0, (t)*64, tid)
#define G1_COMPUTE(b) compute_stage(aB, bB, (b), c)
    PIPE_LOOP(8, G1_ISSUE, G1_COMPUTE);
#undef G1_ISSUE
#undef G1_COMPUTE

    const int sect = n0 >> 9;             // 0=q 1=k 2=v
#pragma unroll
    for (int nf = 0; nf < 4; nf++) {
        const int col = n0 + wn + nf*8 + 2*tig;
        const int h   = (col >> 6) & 7;
        const int d   = col & 63;
        const float b0v = bias[col], b1v = bias[col+1];
        const int  fi  = (d & 31) >> 1;
        const bool axx = (d < 32);
#pragma unroll
        for (int mf = 0; mf < 4; mf++) {
#pragma unroll
            for (int hf = 0; hf < 2; hf++) {
                const int r    = m0 + wm + mf*16 + gid + 8*hf;
                const int bidx = r >> 14;
                const int t    = r & (NN-1);
                float v0 = c[mf][nf][2*hf]   + b0v;
                float v1 = c[mf][nf][2*hf+1] + b1v;
                const size_t base = ((size_t)(bidx*HH + h)*NN + t)*DD + d;
                if (sect == 2) {
                    *(__half2*)(g_v + base) = __floats2half2_rn(v0, v1);
                } else {
                    const int pos = axx ? (t & 127) : (t >> 7);
                    const float2 cs = *(const float2*)(g_trig + ((pos << 4) + fi)*2);
                    float orr = v0*cs.x - v1*cs.y;
                    float oii = v0*cs.y + v1*cs.x;
                    orr = (orr > 0.f) ? orr + 1.f : __expf(orr);
                    oii = (oii > 0.f) ? oii + 1.f : __expf(oii);
                    __half* dst = (sect == 0) ? g_q : g_k;
                    *(__half2*)(dst + base) = __floats2half2_rn(orr, oii);
                }
            }
        }
    }
}

// ---------------------------------------------------------------------------
// GEMM2: out = q'' @ M_stack[b] * 2^-20 + b_proj
// ---------------------------------------------------------------------------
__global__ __launch_bounds__(256, 2) void gemm_proj_kernel(
    const float* __restrict__ bias,
    float* __restrict__ out)
{
    extern __shared__ __half smp[];
    __shared__ __align__(8) uint64_t mbars[6];
    const uint32_t smbase = smem_u32(smp);
    const uint32_t mbF = smem_u32(&mbars[0]);
    const uint32_t mbE = smem_u32(&mbars[3]);
    const int tid  = threadIdx.x;
    const int warp = tid >> 5, lane = tid & 31;
    const int gid  = lane >> 2, tig = lane & 3;
    const int m0 = blockIdx.y << 7, n0 = blockIdx.x << 7;
    const int wm = (warp >> 2) << 6;
    const int wn = (warp & 3) << 5;
    const __half* gB = g_mt + (size_t)(blockIdx.y >> 7)*CC*CC;

    const uint32_t aB = a_frag_base(smbase, wm, lane);
    const uint32_t bB = b_frag_base(smbase, wn, lane);

    float c[4][4][4];
#pragma unroll
    for (int i = 0; i < 4; i++)
#pragma unroll
        for (int j = 0; j < 4; j++)
#pragma unroll
            for (int r = 0; r < 4; r++) c[i][j][r] = 0.f;

#define G2_ISSUE(t)   issue_stage(smbase, (t)%3, g_attn, gB, m0, n0, (t)*64, tid)
#define G2_COMPUTE(b) compute_stage(aB, bB, (b), c)
    PIPE_LOOP(8, G2_ISSUE, G2_COMPUTE);
#undef G2_ISSUE
#undef G2_COMPUTE

#pragma unroll
    for (int nf = 0; nf < 4; nf++) {
        const int col = n0 + wn + nf*8 + 2*tig;
        const float b0v = bias[col], b1v = bias[col+1];
#pragma unroll
        for (int mf = 0; mf < 4; mf++) {
#pragma unroll
            for (int hf = 0; hf < 2; hf++) {
                const int r = m0 + wm + mf*16 + gid + 8*hf;
                *(float2*)(out + (size_t)r*CC + col) =
                    make_float2(c[mf][nf][2*hf]*QSCALE_INV + b0v,
                                c[mf][nf][2*hf+1]*QSCALE_INV + b1v);
            }
        }
    }
}

// ---------------------------------------------------------------------------
// kv[b,h,d,e] = sum_n k[n,d] v[n,e];  ksum via ones-column (col 64).
// fp16 mma, trans-ldmatrix, 3-stage cp.async + mbarrier pipeline.
// ---------------------------------------------------------------------------
#define KT_S 72   // k tile stride (halves)
#define VT_S 88   // v tile stride (halves)
#define KV_STG_H (64*KT_S + 64*VT_S)     // 10240 halves per stage
#define KV_SMEM_BYTES (3 * KV_STG_H * 2) // 61440

__device__ __forceinline__ void kv_issue(
    uint32_t smbase, int stage, const __half* kb, const __half* vb,
    int n0, int tid)
{
    const uint32_t stB = smbase + stage*(KV_STG_H*2);
#pragma unroll
    for (int i = 0; i < 2; i++) {
        const int lin = i*256 + tid;
        const int row = lin >> 3, c8 = (lin & 7) << 3;
        CP_ASYNC_16(stB + (row*KT_S + c8)*2,
                    kb + (size_t)(n0 + row)*DD + c8);
        CP_ASYNC_16(stB + (64*KT_S + row*VT_S + c8)*2,
                    vb + (size_t)(n0 + row)*DD + c8);
    }
}

__global__ __launch_bounds__(256, 2) void kv_mma_kernel() {
    extern __shared__ __half kvsm[];
    __shared__ __align__(8) uint64_t mbars[6];
    const uint32_t smbase = smem_u32(kvsm);
    const uint32_t mbF = smem_u32(&mbars[0]);
    const uint32_t mbE = smem_u32(&mbars[3]);

    const int tid  = threadIdx.x;
    const int warp = tid >> 5, lane = tid & 31;
    const int gid  = lane >> 2, tig = lane & 3;
    const int bh    = blockIdx.x;
    const int nbase = blockIdx.y << 10;
    const int d0   = (warp & 3) << 4;     // m-tile (d)
    const int srow = (warp >> 2) << 5;    // seq slice 0/32

    if (tid < 64) {
#pragma unroll
        for (int st = 0; st < 3; st++) {
            __half* Vt = kvsm + st*KV_STG_H + 64*KT_S;
            Vt[tid*VT_S + 64] = __float2half(1.f);
#pragma unroll
            for (int j = 65; j < 80; j++) Vt[tid*VT_S + j] = __float2half(0.f);
        }
    }
    __syncthreads();

    float c[9][4];
#pragma unroll
    for (int t = 0; t < 9; t++)
#pragma unroll
        for (int r = 0; r < 4; r++) c[t][r] = 0.f;

    const __half* kb = g_k + (size_t)bh*NN*DD;
    const __half* vb = g_v + (size_t)bh*NN*DD;

    const int at_row = ((lane >> 4) << 3) + (lane & 7);
    const int at_col = d0 + (((lane >> 3) & 1) << 3);
    const int bt_row = (((lane >> 3) & 1) << 3) + (lane & 7);
    const int bt_coff = ((lane >> 4) << 3);

#define KV_ISSUE(t) kv_issue(smbase, (t)%3, kb, vb, nbase + (t)*64, tid)
#define KV_COMPUTE(bufi)                                                       \
    do {                                                                       \
        const uint32_t ktB = smbase + (bufi)*(KV_STG_H*2);                     \
        const uint32_t vtB = ktB + 64*KT_S*2;                                  \
        _Pragma("unroll")                                                      \
        for (int ks = 0; ks < 2; ks++) {                                       \
            const int s16 = srow + ks*16;                                      \
            unsigned a[4], b[5][4];                                            \
            ldsm_x4_t(a, ktB + ((s16 + at_row)*KT_S + at_col)*2);              \
            _Pragma("unroll")                                                  \
            for (int bt = 0; bt < 5; bt++)                                     \
                ldsm_x4_t(b[bt], vtB + ((s16 + bt_row)*VT_S + bt*16 + bt_coff)*2); \
            _Pragma("unroll")                                                  \
            for (int t2 = 0; t2 < 9; t2++)                                     \
                mma16(c[t2], a, &b[t2 >> 1][(t2 & 1) * 2]);                    \
        }                                                                      \
    } while (0)
    PIPE_LOOP(16, KV_ISSUE, KV_COMPUTE);
#undef KV_ISSUE
#undef KV_COMPUTE

    float* kvp = g_kv + bh*DD*DD;
#pragma unroll
    for (int t = 0; t < 8; t++) {
        const int e = t*8 + 2*tig;
        atomicAdd(&kvp[(d0+gid)*DD + e],       c[t][0]);
        atomicAdd(&kvp[(d0+gid)*DD + e + 1],   c[t][1]);
        atomicAdd(&kvp[(d0+gid+8)*DD + e],     c[t][2]);
        atomicAdd(&kvp[(d0+gid+8)*DD + e + 1], c[t][3]);
    }
    if (tig == 0) {
        atomicAdd(&g_ksum[bh*DD + d0 + gid],     c[8][0]);
        atomicAdd(&g_ksum[bh*DD + d0 + gid + 8], c[8][2]);
    }
}

// ---------------------------------------------------------------------------
// M^T[b][j][h*64+d] = sum_e kv[b,h,d,e] * w_proj[h*64+e, j]   (half out)
// ---------------------------------------------------------------------------
__global__ __launch_bounds__(256) void m_precompute_kernel(
    const float* __restrict__ w_proj)
{
    __shared__ float kvs[64][65];
    __shared__ float ws[64][65];
    const int b = blockIdx.x, h = blockIdx.y, j0 = blockIdx.z << 6;
    const int tid = threadIdx.x;
    const float* kvp = g_kv + ((b*HH + h)*DD*DD);

#pragma unroll
    for (int i = 0; i < 16; i++) {
        const int lin = i*256 + tid;          // 4096
        const int r = lin >> 6, cidx = lin & 63;
        kvs[r][cidx] = kvp[r*DD + cidx];
        ws[r][cidx]  = w_proj[(size_t)(h*DD + r)*CC + j0 + cidx];
    }
    __syncthreads();

    const int d = tid & 63;
    const int jg = tid >> 6;                  // 0..3
#pragma unroll
    for (int jj = 0; jj < 16; jj++) {
        const int j = jg*16 + jj;
        float acc = 0.f;
#pragma unroll
        for (int e = 0; e < 64; e++)
            acc = fmaf(kvs[d][e], ws[e][j], acc);
        g_mt[((size_t)b*CC + j0 + j)*CC + h*DD + d] = __float2half_rn(acc);
    }
}

// ---------------------------------------------------------------------------
// q''[b*NN+n][h*64+d] = q[b,h,n,d] * 2^20 / (q.ksum + 1e-6)
// ---------------------------------------------------------------------------
__global__ __launch_bounds__(256) void zq_kernel() {
    const int bh = blockIdx.x, b = bh >> 3, h = bh & 7;
    const int tid = threadIdx.x;
    const int r8 = tid >> 3;
    const int t8 = tid & 7;
    const int n  = (blockIdx.y << 5) + r8;

    uint4 u = *(const uint4*)(g_q + ((size_t)bh*NN + n)*DD + t8*8);
    float f[8];
    {
        __half2* hp = (__half2*)&u;
#pragma unroll
        for (int i = 0; i < 4; i++) {
            float2 t = __half22float2(hp[i]);
            f[2*i] = t.x; f[2*i+1] = t.y;
        }
    }
    const float* ks = g_ksum + bh*DD + t8*8;
    float dot = 0.f;
#pragma unroll
    for (int i = 0; i < 8; i++) dot = fmaf(f[i], ks[i], dot);
    dot += __shfl_xor_sync(0xffffffffu, dot, 1);
    dot += __shfl_xor_sync(0xffffffffu, dot, 2);
    dot += __shfl_xor_sync(0xffffffffu, dot, 4);
    const float z = QSCALE / (dot + 1e-6f);

    __half2 o[4];
#pragma unroll
    for (int i = 0; i < 4; i++)
        o[i] = __floats2half2_rn(f[2*i]*z, f[2*i+1]*z);
    *(uint4*)(g_attn + ((size_t)b*NN + n)*CC + h*DD + t8*8) =
        *(uint4*)o;
}

// ---------------------------------------------------------------------------
extern "C" void kernel_launch(void* const* d_in, const int* in_sizes, int n_in,
                              void* d_out, int out_size) {
    const float* x      = (const float*)d_in[0];
    const float* w_qkv  = (const float*)d_in[1];
    const float* b_qkv  = (const float*)d_in[2];
    const float* w_proj = (const float*)d_in[3];
    const float* b_proj = (const float*)d_in[4];
    float* out = (float*)d_out;

    cudaFuncSetAttribute(gemm_qkv_kernel,
        cudaFuncAttributeMaxDynamicSharedMemorySize, SMEM_PIPE_BYTES);
    cudaFuncSetAttribute(gemm_proj_kernel,
        cudaFuncAttributeMaxDynamicSharedMemorySize, SMEM_PIPE_BYTES);
    cudaFuncSetAttribute(kv_mma_kernel,
        cudaFuncAttributeMaxDynamicSharedMemorySize, KV_SMEM_BYTES);

    __half* wt1p;
    cudaGetSymbolAddress((void**)&wt1p, g_wt1);

    init_kernel<<<512, 256>>>();
    convert_x_kernel<<<16384, 256>>>(x);
    transpose_w_kernel<<<dim3(48, 16), dim3(32, 8)>>>(w_qkv, wt1p, W3);
    gemm_qkv_kernel<<<dim3(12, 512), 256, SMEM_PIPE_BYTES>>>(b_qkv);
    kv_mma_kernel<<<dim3(32, 16), 256, KV_SMEM_BYTES>>>();
    m_precompute_kernel<<<dim3(4, 8, 8), 256>>>(w_proj);
    zq_kernel<<<dim3(32, 512), 256>>>();
    gemm_proj_kernel<<<dim3(4, 512), 256, SMEM_PIPE_BYTES>>>(b_proj, out);
}